// round 2
// baseline (speedup 1.0000x reference)
#include <cuda_runtime.h>
#include <cuda_bf16.h>

// Problem constants
#define S_DIM   64
#define N_DIM   384
#define C_IN    64
#define C_H     32
#define C_OUT   128
#define KTOT    1024          // C_H*C_H
#define AB_COLS (N_DIM * C_H) // 12288
#define LN_EPS  1e-5f

// Scratch (allocation-free rule: __device__ globals)
__device__ float g_A[S_DIM * AB_COLS];     // A[s][n*32+c], masked projection a
__device__ float g_B[S_DIM * AB_COLS];     // B[s][n*32+d], masked projection b
__device__ float g_WoT[KTOT * C_OUT];      // WoT[k][o] = Wo[o][k]

// ---------------------------------------------------------------------------
// Kernel 1: LayerNorm + dual projection + mask  ->  g_A, g_B
// One warp per (s,n) row. Block = 256 threads = 8 rows.
// ---------------------------------------------------------------------------
__global__ __launch_bounds__(256) void prep_kernel(
    const float* __restrict__ m, const int* __restrict__ mask,
    const float* __restrict__ gamma, const float* __restrict__ beta,
    const float* __restrict__ Wa, const float* __restrict__ Wb)
{
    __shared__ float sWaT[C_IN * C_H];   // [k][c] transposed, conflict-free reads
    __shared__ float sWbT[C_IN * C_H];
    __shared__ float sMn[8][C_IN];

    for (int i = threadIdx.x; i < C_H * C_IN; i += 256) {
        int c = i >> 6, k = i & 63;      // Wa[c][k]
        sWaT[k * C_H + c] = Wa[i];
        sWbT[k * C_H + c] = Wb[i];
    }
    __syncthreads();

    int warp = threadIdx.x >> 5;
    int lane = threadIdx.x & 31;
    int row  = blockIdx.x * 8 + warp;          // row = s*384 + n
    if (row >= S_DIM * N_DIM) return;

    const float* mp = m + (size_t)row * C_IN;
    float v0 = mp[lane], v1 = mp[lane + 32];

    float sum = v0 + v1;
    #pragma unroll
    for (int o = 16; o; o >>= 1) sum += __shfl_xor_sync(0xffffffffu, sum, o);
    float mu = sum * (1.f / 64.f);
    float d0 = v0 - mu, d1 = v1 - mu;
    float sq = d0 * d0 + d1 * d1;
    #pragma unroll
    for (int o = 16; o; o >>= 1) sq += __shfl_xor_sync(0xffffffffu, sq, o);
    float inv = rsqrtf(sq * (1.f / 64.f) + LN_EPS);

    float mn0 = d0 * inv * gamma[lane]      + beta[lane];
    float mn1 = d1 * inv * gamma[lane + 32] + beta[lane + 32];
    sMn[warp][lane]      = mn0;
    sMn[warp][lane + 32] = mn1;
    __syncwarp();

    float mf = (float)mask[row];
    float aa = 0.f, bb = 0.f;
    #pragma unroll
    for (int k = 0; k < C_IN; k++) {
        float x = sMn[warp][k];
        aa += x * sWaT[k * C_H + lane];
        bb += x * sWbT[k * C_H + lane];
    }
    int s = row / N_DIM, n = row % N_DIM;
    g_A[s * AB_COLS + n * C_H + lane] = aa * mf;
    g_B[s * AB_COLS + n * C_H + lane] = bb * mf;
}

// ---------------------------------------------------------------------------
// Kernel 2: transpose Wo[o][k] -> WoT[k][o]
// ---------------------------------------------------------------------------
__global__ void transpose_wo(const float* __restrict__ Wo)
{
    int idx = blockIdx.x * 256 + threadIdx.x;      // 131072 elements
    if (idx < C_OUT * KTOT) {
        int o = idx >> 10, k = idx & 1023;
        g_WoT[k * C_OUT + o] = Wo[idx];
    }
}

// ---------------------------------------------------------------------------
// Kernel 3: main fused kernel. One CTA = 4x4 (i,j) tile.
//   Stage 1: load A-tile/B-tile (64 x 128 each) to smem
//   Stage 2: GEMM1  Z(128x128) = A^T B  (K=64), 8x8 register micro-tiles
//   Stage 3: GEMM2  out(16x128) = Zflat(16x1024) @ WoT, 4-way k-split
//   Stage 4: smem reduction, /denom, +bo, store
// ---------------------------------------------------------------------------
#define TI 4
#define TJ 4
#define PADZ 132
#define SMEM_FLOATS (128 * PADZ + 32)   // Zs + invd scratch

__global__ __launch_bounds__(256) void main_kernel(
    const int* __restrict__ mask,
    const float* __restrict__ bo,
    float* __restrict__ out)
{
    extern __shared__ float sm[];
    float* As    = sm;                 // [64][128] (stage 1/2 only)
    float* Bs    = sm + 8192;          // [64][128]
    float* Zs    = sm;                 // [128][PADZ] (stage 2/3, aliases As/Bs)
    float* red   = sm;                 // [4][16][128] partials (stage 4, aliases Zs)
    float* sInvd = sm + 128 * PADZ;    // [16]

    const int t  = threadIdx.x;
    const int ti = blockIdx.x, tj = blockIdx.y;

    // --- pairwise mask denominators (16 pairs), fully unrolled for MLP ---
    if (t < 16) {
        int ii = t >> 2, jj = t & 3;
        const int* mi = mask + ti * TI + ii;
        const int* mj = mask + tj * TJ + jj;
        int dsum = 0;
        #pragma unroll
        for (int s = 0; s < S_DIM; s++)
            dsum += mi[s * N_DIM] * mj[s * N_DIM];
        float d = (float)dsum;
        sInvd[t] = 1.f / fmaxf(d, 1.f);
    }

    // --- stage 1: load tiles ---
    {
        const float4* A4 = (const float4*)g_A;   // row stride 3072 float4
        const float4* B4 = (const float4*)g_B;
        float4* As4 = (float4*)As;
        float4* Bs4 = (float4*)Bs;
        #pragma unroll
        for (int idx = t; idx < 64 * 32; idx += 256) {
            int k = idx >> 5, q = idx & 31;
            As4[k * 32 + q] = A4[k * 3072 + ti * 32 + q];
            Bs4[k * 32 + q] = B4[k * 3072 + tj * 32 + q];
        }
    }
    __syncthreads();

    // --- stage 2: GEMM1 Z = A^T B, thread (tx,ty) owns 8x8 ---
    const int tx = t & 15, ty = t >> 4;
    float acc[8][8];
    #pragma unroll
    for (int iy = 0; iy < 8; iy++)
        #pragma unroll
        for (int ix = 0; ix < 8; ix++) acc[iy][ix] = 0.f;

    #pragma unroll 4
    for (int k = 0; k < 64; k++) {
        float av[8], bv[8];
        *(float4*)&av[0] = *(const float4*)&As[k * 128 + ty * 8];
        *(float4*)&av[4] = *(const float4*)&As[k * 128 + ty * 8 + 4];
        *(float4*)&bv[0] = *(const float4*)&Bs[k * 128 + tx * 8];
        *(float4*)&bv[4] = *(const float4*)&Bs[k * 128 + tx * 8 + 4];
        #pragma unroll
        for (int iy = 0; iy < 8; iy++)
            #pragma unroll
            for (int ix = 0; ix < 8; ix++)
                acc[iy][ix] += av[iy] * bv[ix];
    }
    __syncthreads();   // As/Bs reads done; Zs may now overwrite

    #pragma unroll
    for (int iy = 0; iy < 8; iy++) {
        int r = ty * 8 + iy;
        *(float4*)&Zs[r * PADZ + tx * 8]     = make_float4(acc[iy][0], acc[iy][1], acc[iy][2], acc[iy][3]);
        *(float4*)&Zs[r * PADZ + tx * 8 + 4] = make_float4(acc[iy][4], acc[iy][5], acc[iy][6], acc[iy][7]);
    }
    __syncthreads();

    // --- stage 3: GEMM2, 4-way k-split: thread = (ks, pg=ii, oi) ---
    const int ks = t >> 6;          // k-slice 0..3 (k in [ks*256, ks*256+256))
    const int t6 = t & 63;
    const int pg = t6 >> 4;         // ii = 0..3
    const int oi = t6 & 15;         // o block: o in [oi*8, oi*8+8)

    float oacc[4][8];               // [jj][u]
    #pragma unroll
    for (int jj = 0; jj < 4; jj++)
        #pragma unroll
        for (int u = 0; u < 8; u++) oacc[jj][u] = 0.f;

    {
        const float4* wp = (const float4*)g_WoT + (size_t)(ks * 256) * 32 + oi * 2;
        const int kc0 = ks * 8;
        #pragma unroll 1
        for (int kc = 0; kc < 8; kc++) {
            const float* zbase = &Zs[(pg * 32 + kc0 + kc) * PADZ];
            #pragma unroll 4
            for (int kd = 0; kd < 32; kd++) {
                float4 w0 = wp[0];
                float4 w1 = wp[1];
                wp += 32;
                float z0 = zbase[kd];
                float z1 = zbase[32 + kd];
                float z2 = zbase[64 + kd];
                float z3 = zbase[96 + kd];
                float wv[8] = {w0.x, w0.y, w0.z, w0.w, w1.x, w1.y, w1.z, w1.w};
                #pragma unroll
                for (int u = 0; u < 8; u++) {
                    oacc[0][u] += z0 * wv[u];
                    oacc[1][u] += z1 * wv[u];
                    oacc[2][u] += z2 * wv[u];
                    oacc[3][u] += z3 * wv[u];
                }
            }
        }
    }
    __syncthreads();   // Zs reads done; red may overwrite

    // --- stage 4: cross-slice reduction + epilogue ---
    #pragma unroll
    for (int jj = 0; jj < 4; jj++) {
        int p = pg * 4 + jj;
        float* rp = &red[(ks * 16 + p) * 128 + oi * 8];
        *(float4*)&rp[0] = make_float4(oacc[jj][0], oacc[jj][1], oacc[jj][2], oacc[jj][3]);
        *(float4*)&rp[4] = make_float4(oacc[jj][4], oacc[jj][5], oacc[jj][6], oacc[jj][7]);
    }
    __syncthreads();

    {
        int p  = t >> 4;            // pair 0..15
        int ob = (t & 15) * 8;      // o base
        int ii = p >> 2, jj = p & 3;
        float invd = sInvd[p];
        int gi = ti * TI + ii, gj = tj * TJ + jj;
        float* op = out + ((size_t)gi * N_DIM + gj) * C_OUT + ob;
        float res[8];
        #pragma unroll
        for (int u = 0; u < 8; u++) {
            float v = red[(0 * 16 + p) * 128 + ob + u]
                    + red[(1 * 16 + p) * 128 + ob + u]
                    + red[(2 * 16 + p) * 128 + ob + u]
                    + red[(3 * 16 + p) * 128 + ob + u];
            res[u] = v * invd + bo[ob + u];
        }
        *(float4*)&op[0] = make_float4(res[0], res[1], res[2], res[3]);
        *(float4*)&op[4] = make_float4(res[4], res[5], res[6], res[7]);
    }
}

// ---------------------------------------------------------------------------
extern "C" void kernel_launch(void* const* d_in, const int* in_sizes, int n_in,
                              void* d_out, int out_size)
{
    const float* m     = (const float*)d_in[0];
    const int*   mask  = (const int*)  d_in[1];
    const float* gamma = (const float*)d_in[2];
    const float* beta  = (const float*)d_in[3];
    const float* Wa    = (const float*)d_in[4];
    const float* Wb    = (const float*)d_in[5];
    const float* Wo    = (const float*)d_in[6];
    const float* bo    = (const float*)d_in[7];
    float* out = (float*)d_out;

    static_assert(SMEM_FLOATS * 4 < 70 * 1024, "smem budget");
    cudaFuncSetAttribute(main_kernel, cudaFuncAttributeMaxDynamicSharedMemorySize,
                         SMEM_FLOATS * (int)sizeof(float));

    prep_kernel<<<(S_DIM * N_DIM) / 8, 256>>>(m, mask, gamma, beta, Wa, Wb);
    transpose_wo<<<(C_OUT * KTOT + 255) / 256, 256>>>(Wo);

    dim3 grid(N_DIM / TI, N_DIM / TJ);
    main_kernel<<<grid, 256, SMEM_FLOATS * (int)sizeof(float)>>>(mask, bo, out);
}

// round 3
// speedup vs baseline: 1.0019x; 1.0019x over previous
#include <cuda_runtime.h>
#include <cuda_bf16.h>

// Problem constants
#define S_DIM   64
#define N_DIM   384
#define C_IN    64
#define C_H     32
#define C_OUT   128
#define KTOT    1024          // C_H*C_H
#define AB_COLS (N_DIM * C_H) // 12288
#define LN_EPS  1e-5f

// Scratch (allocation-free rule: __device__ globals)
__device__ float g_A[S_DIM * AB_COLS];     // A[s][n*32+c], masked projection a
__device__ float g_B[S_DIM * AB_COLS];     // B[s][n*32+d], masked projection b
__device__ float g_WoT[KTOT * C_OUT];      // WoT[k][o] = Wo[o][k]

// ---------------------------------------------------------------------------
// Kernel 1: LayerNorm + dual projection + mask  ->  g_A, g_B
// One warp per (s,n) row. Block = 256 threads = 8 rows.
// ---------------------------------------------------------------------------
__global__ __launch_bounds__(256) void prep_kernel(
    const float* __restrict__ m, const int* __restrict__ mask,
    const float* __restrict__ gamma, const float* __restrict__ beta,
    const float* __restrict__ Wa, const float* __restrict__ Wb)
{
    __shared__ float sWaT[C_IN * C_H];   // [k][c] transposed, conflict-free reads
    __shared__ float sWbT[C_IN * C_H];
    __shared__ float sMn[8][C_IN];

    for (int i = threadIdx.x; i < C_H * C_IN; i += 256) {
        int c = i >> 6, k = i & 63;      // Wa[c][k]
        sWaT[k * C_H + c] = Wa[i];
        sWbT[k * C_H + c] = Wb[i];
    }
    __syncthreads();

    int warp = threadIdx.x >> 5;
    int lane = threadIdx.x & 31;
    int row  = blockIdx.x * 8 + warp;          // row = s*384 + n
    if (row >= S_DIM * N_DIM) return;

    const float* mp = m + (size_t)row * C_IN;
    float v0 = mp[lane], v1 = mp[lane + 32];

    float sum = v0 + v1;
    #pragma unroll
    for (int o = 16; o; o >>= 1) sum += __shfl_xor_sync(0xffffffffu, sum, o);
    float mu = sum * (1.f / 64.f);
    float d0 = v0 - mu, d1 = v1 - mu;
    float sq = d0 * d0 + d1 * d1;
    #pragma unroll
    for (int o = 16; o; o >>= 1) sq += __shfl_xor_sync(0xffffffffu, sq, o);
    float inv = rsqrtf(sq * (1.f / 64.f) + LN_EPS);

    float mn0 = d0 * inv * gamma[lane]      + beta[lane];
    float mn1 = d1 * inv * gamma[lane + 32] + beta[lane + 32];
    sMn[warp][lane]      = mn0;
    sMn[warp][lane + 32] = mn1;
    __syncwarp();

    float mf = (float)mask[row];
    float aa = 0.f, bb = 0.f;
    #pragma unroll
    for (int k = 0; k < C_IN; k++) {
        float x = sMn[warp][k];
        aa += x * sWaT[k * C_H + lane];
        bb += x * sWbT[k * C_H + lane];
    }
    int s = row / N_DIM, n = row % N_DIM;
    g_A[s * AB_COLS + n * C_H + lane] = aa * mf;
    g_B[s * AB_COLS + n * C_H + lane] = bb * mf;
}

// ---------------------------------------------------------------------------
// Kernel 2: transpose Wo[o][k] -> WoT[k][o]
// ---------------------------------------------------------------------------
__global__ void transpose_wo(const float* __restrict__ Wo)
{
    int idx = blockIdx.x * 256 + threadIdx.x;      // 131072 elements
    if (idx < C_OUT * KTOT) {
        int o = idx >> 10, k = idx & 1023;
        g_WoT[k * C_OUT + o] = Wo[idx];
    }
}

// ---------------------------------------------------------------------------
// Kernel 3: main fused kernel. One CTA = 4x4 (i,j) tile.
//   Stage 1: load A-tile/B-tile (64 x 128 each) to smem
//   Stage 2: GEMM1  Z(128x128) = A^T B  (K=64), 8x8 register micro-tiles
//   Stage 3: GEMM2  out(16x128) = Zflat(16x1024) @ WoT, 4-way k-split
//   Stage 4: smem reduction, /denom, +bo, store
// ---------------------------------------------------------------------------
#define TI 4
#define TJ 4
#define PADZ 132
#define SMEM_FLOATS (128 * PADZ + 32)   // Zs + invd scratch

__global__ __launch_bounds__(256) void main_kernel(
    const int* __restrict__ mask,
    const float* __restrict__ bo,
    float* __restrict__ out)
{
    extern __shared__ float sm[];
    float* As    = sm;                 // [64][128] (stage 1/2 only)
    float* Bs    = sm + 8192;          // [64][128]
    float* Zs    = sm;                 // [128][PADZ] (stage 2/3, aliases As/Bs)
    float* red   = sm;                 // [4][16][128] partials (stage 4, aliases Zs)
    float* sInvd = sm + 128 * PADZ;    // [16]

    const int t  = threadIdx.x;
    const int ti = blockIdx.x, tj = blockIdx.y;

    // --- pairwise mask denominators (16 pairs), fully unrolled for MLP ---
    if (t < 16) {
        int ii = t >> 2, jj = t & 3;
        const int* mi = mask + ti * TI + ii;
        const int* mj = mask + tj * TJ + jj;
        int dsum = 0;
        #pragma unroll
        for (int s = 0; s < S_DIM; s++)
            dsum += mi[s * N_DIM] * mj[s * N_DIM];
        float d = (float)dsum;
        sInvd[t] = 1.f / fmaxf(d, 1.f);
    }

    // --- stage 1: load tiles ---
    {
        const float4* A4 = (const float4*)g_A;   // row stride 3072 float4
        const float4* B4 = (const float4*)g_B;
        float4* As4 = (float4*)As;
        float4* Bs4 = (float4*)Bs;
        #pragma unroll
        for (int idx = t; idx < 64 * 32; idx += 256) {
            int k = idx >> 5, q = idx & 31;
            As4[k * 32 + q] = A4[k * 3072 + ti * 32 + q];
            Bs4[k * 32 + q] = B4[k * 3072 + tj * 32 + q];
        }
    }
    __syncthreads();

    // --- stage 2: GEMM1 Z = A^T B, thread (tx,ty) owns 8x8 ---
    const int tx = t & 15, ty = t >> 4;
    float acc[8][8];
    #pragma unroll
    for (int iy = 0; iy < 8; iy++)
        #pragma unroll
        for (int ix = 0; ix < 8; ix++) acc[iy][ix] = 0.f;

    #pragma unroll 4
    for (int k = 0; k < 64; k++) {
        float av[8], bv[8];
        *(float4*)&av[0] = *(const float4*)&As[k * 128 + ty * 8];
        *(float4*)&av[4] = *(const float4*)&As[k * 128 + ty * 8 + 4];
        *(float4*)&bv[0] = *(const float4*)&Bs[k * 128 + tx * 8];
        *(float4*)&bv[4] = *(const float4*)&Bs[k * 128 + tx * 8 + 4];
        #pragma unroll
        for (int iy = 0; iy < 8; iy++)
            #pragma unroll
            for (int ix = 0; ix < 8; ix++)
                acc[iy][ix] += av[iy] * bv[ix];
    }
    __syncthreads();   // As/Bs reads done; Zs may now overwrite

    #pragma unroll
    for (int iy = 0; iy < 8; iy++) {
        int r = ty * 8 + iy;
        *(float4*)&Zs[r * PADZ + tx * 8]     = make_float4(acc[iy][0], acc[iy][1], acc[iy][2], acc[iy][3]);
        *(float4*)&Zs[r * PADZ + tx * 8 + 4] = make_float4(acc[iy][4], acc[iy][5], acc[iy][6], acc[iy][7]);
    }
    __syncthreads();

    // --- stage 3: GEMM2, 4-way k-split: thread = (ks, pg=ii, oi) ---
    const int ks = t >> 6;          // k-slice 0..3 (k in [ks*256, ks*256+256))
    const int t6 = t & 63;
    const int pg = t6 >> 4;         // ii = 0..3
    const int oi = t6 & 15;         // o block: o in [oi*8, oi*8+8)

    float oacc[4][8];               // [jj][u]
    #pragma unroll
    for (int jj = 0; jj < 4; jj++)
        #pragma unroll
        for (int u = 0; u < 8; u++) oacc[jj][u] = 0.f;

    {
        const float4* wp = (const float4*)g_WoT + (size_t)(ks * 256) * 32 + oi * 2;
        const int kc0 = ks * 8;
        #pragma unroll 1
        for (int kc = 0; kc < 8; kc++) {
            const float* zbase = &Zs[(pg * 32 + kc0 + kc) * PADZ];
            #pragma unroll 4
            for (int kd = 0; kd < 32; kd++) {
                float4 w0 = wp[0];
                float4 w1 = wp[1];
                wp += 32;
                float z0 = zbase[kd];
                float z1 = zbase[32 + kd];
                float z2 = zbase[64 + kd];
                float z3 = zbase[96 + kd];
                float wv[8] = {w0.x, w0.y, w0.z, w0.w, w1.x, w1.y, w1.z, w1.w};
                #pragma unroll
                for (int u = 0; u < 8; u++) {
                    oacc[0][u] += z0 * wv[u];
                    oacc[1][u] += z1 * wv[u];
                    oacc[2][u] += z2 * wv[u];
                    oacc[3][u] += z3 * wv[u];
                }
            }
        }
    }
    __syncthreads();   // Zs reads done; red may overwrite

    // --- stage 4: cross-slice reduction + epilogue ---
    #pragma unroll
    for (int jj = 0; jj < 4; jj++) {
        int p = pg * 4 + jj;
        float* rp = &red[(ks * 16 + p) * 128 + oi * 8];
        *(float4*)&rp[0] = make_float4(oacc[jj][0], oacc[jj][1], oacc[jj][2], oacc[jj][3]);
        *(float4*)&rp[4] = make_float4(oacc[jj][4], oacc[jj][5], oacc[jj][6], oacc[jj][7]);
    }
    __syncthreads();

    {
        int p  = t >> 4;            // pair 0..15
        int ob = (t & 15) * 8;      // o base
        int ii = p >> 2, jj = p & 3;
        float invd = sInvd[p];
        int gi = ti * TI + ii, gj = tj * TJ + jj;
        float* op = out + ((size_t)gi * N_DIM + gj) * C_OUT + ob;
        float res[8];
        #pragma unroll
        for (int u = 0; u < 8; u++) {
            float v = red[(0 * 16 + p) * 128 + ob + u]
                    + red[(1 * 16 + p) * 128 + ob + u]
                    + red[(2 * 16 + p) * 128 + ob + u]
                    + red[(3 * 16 + p) * 128 + ob + u];
            res[u] = v * invd + bo[ob + u];
        }
        *(float4*)&op[0] = make_float4(res[0], res[1], res[2], res[3]);
        *(float4*)&op[4] = make_float4(res[4], res[5], res[6], res[7]);
    }
}

// ---------------------------------------------------------------------------
extern "C" void kernel_launch(void* const* d_in, const int* in_sizes, int n_in,
                              void* d_out, int out_size)
{
    const float* m     = (const float*)d_in[0];
    const int*   mask  = (const int*)  d_in[1];
    const float* gamma = (const float*)d_in[2];
    const float* beta  = (const float*)d_in[3];
    const float* Wa    = (const float*)d_in[4];
    const float* Wb    = (const float*)d_in[5];
    const float* Wo    = (const float*)d_in[6];
    const float* bo    = (const float*)d_in[7];
    float* out = (float*)d_out;

    static_assert(SMEM_FLOATS * 4 < 70 * 1024, "smem budget");
    cudaFuncSetAttribute(main_kernel, cudaFuncAttributeMaxDynamicSharedMemorySize,
                         SMEM_FLOATS * (int)sizeof(float));

    prep_kernel<<<(S_DIM * N_DIM) / 8, 256>>>(m, mask, gamma, beta, Wa, Wb);
    transpose_wo<<<(C_OUT * KTOT + 255) / 256, 256>>>(Wo);

    dim3 grid(N_DIM / TI, N_DIM / TJ);
    main_kernel<<<grid, 256, SMEM_FLOATS * (int)sizeof(float)>>>(mask, bo, out);
}

// round 5
// speedup vs baseline: 6.4765x; 6.4641x over previous
#include <cuda_runtime.h>
#include <cuda_fp16.h>
#include <cstdint>

#define N_DIM 384
#define S_DIM 64
#define C_IN  64
#define C_H   32
#define C_OUT 128
#define LN_EPS 1e-5f

// ---------------- device scratch ----------------
__device__ __half g_A[N_DIM * C_H * S_DIM];      // [n][c][s] fp16
__device__ __half g_B[N_DIM * C_H * S_DIM];      // [n][d][s] fp16
__device__ __half g_W[16 * C_OUT * 64];          // [cidx][o][kk] fp16
__device__ unsigned long long g_mbits[N_DIM];

#define SWZ(b) ((b) ^ (((b) >> 3) & 0x70))

__device__ __forceinline__ uint32_t smem_u32(const void* p) {
    uint32_t a;
    asm("{ .reg .u64 t; cvta.to.shared.u64 t, %1; cvt.u32.u64 %0, t; }" : "=r"(a) : "l"(p));
    return a;
}
__device__ __forceinline__ void ldsm4(uint32_t r[4], uint32_t a) {
    asm volatile("ldmatrix.sync.aligned.m8n8.x4.shared.b16 {%0,%1,%2,%3}, [%4];"
                 : "=r"(r[0]), "=r"(r[1]), "=r"(r[2]), "=r"(r[3]) : "r"(a));
}
__device__ __forceinline__ void mma16816(float c[4], const uint32_t a[4], const uint32_t b[2]) {
    asm volatile("mma.sync.aligned.m16n8k16.row.col.f32.f16.f16.f32 "
                 "{%0,%1,%2,%3}, {%4,%5,%6,%7}, {%8,%9}, {%0,%1,%2,%3};"
                 : "+f"(c[0]), "+f"(c[1]), "+f"(c[2]), "+f"(c[3])
                 : "r"(a[0]), "r"(a[1]), "r"(a[2]), "r"(a[3]), "r"(b[0]), "r"(b[1]));
}
#define CP16(dst, src) asm volatile("cp.async.cg.shared.global [%0], [%1], 16;" :: "r"(dst), "l"(src))
#define CP_COMMIT()    asm volatile("cp.async.commit_group;" ::: "memory")
#define CP_WAIT(n)     asm volatile("cp.async.wait_group %0;" :: "n"(n) : "memory")

// ---------------------------------------------------------------------------
// prep: LN + dual projection + mask -> fp16 [n][ch][s]; mask bitmasks
// one block per n
// ---------------------------------------------------------------------------
__global__ __launch_bounds__(256) void prep_kernel(
    const float* __restrict__ m, const int* __restrict__ mask,
    const float* __restrict__ gamma, const float* __restrict__ beta,
    const float* __restrict__ Wa, const float* __restrict__ Wb)
{
    __shared__ float sWaT[C_IN * C_H];
    __shared__ float sWbT[C_IN * C_H];
    __shared__ float sMn[8][C_IN];
    __shared__ float sa[C_H * 65];
    __shared__ float sb[C_H * 65];

    int tid = threadIdx.x, w = tid >> 5, l = tid & 31;
    int n = blockIdx.x;

    for (int i = tid; i < C_H * C_IN; i += 256) {
        int c = i >> 6, k = i & 63;
        sWaT[k * C_H + c] = Wa[i];
        sWbT[k * C_H + c] = Wb[i];
    }
    __syncthreads();

    float gam0 = gamma[l], gam1 = gamma[l + 32];
    float bet0 = beta[l],  bet1 = beta[l + 32];

    for (int it = 0; it < 8; it++) {
        int s = it * 8 + w;
        int row = s * N_DIM + n;
        const float* mp = m + (size_t)row * C_IN;
        float v0 = mp[l], v1 = mp[l + 32];
        float sum = v0 + v1;
        #pragma unroll
        for (int o = 16; o; o >>= 1) sum += __shfl_xor_sync(0xffffffffu, sum, o);
        float mu = sum * (1.f / 64.f);
        float d0 = v0 - mu, d1 = v1 - mu;
        float sq = d0 * d0 + d1 * d1;
        #pragma unroll
        for (int o = 16; o; o >>= 1) sq += __shfl_xor_sync(0xffffffffu, sq, o);
        float inv = rsqrtf(sq * (1.f / 64.f) + LN_EPS);
        sMn[w][l]      = d0 * inv * gam0 + bet0;
        sMn[w][l + 32] = d1 * inv * gam1 + bet1;
        __syncwarp();
        float mf = (float)mask[row];
        float aa = 0.f, bb = 0.f;
        #pragma unroll
        for (int k = 0; k < C_IN; k++) {
            float x = sMn[w][k];
            aa += x * sWaT[k * C_H + l];
            bb += x * sWbT[k * C_H + l];
        }
        sa[l * 65 + s] = aa * mf;
        sb[l * 65 + s] = bb * mf;
        __syncwarp();
    }
    __syncthreads();

    for (int e = tid; e < C_H * S_DIM; e += 256) {
        int c = e >> 6, s = e & 63;
        g_A[n * 2048 + e] = __float2half(sa[c * 65 + s]);
        g_B[n * 2048 + e] = __float2half(sb[c * 65 + s]);
    }

    if (w == 0) {
        unsigned b0 = __ballot_sync(0xffffffffu, mask[l * N_DIM + n] != 0);
        unsigned b1 = __ballot_sync(0xffffffffu, mask[(l + 32) * N_DIM + n] != 0);
        if (l == 0) g_mbits[n] = (unsigned long long)b0 | ((unsigned long long)b1 << 32);
    }
}

// ---------------------------------------------------------------------------
// Wo gather: g_W[cidx=sl*4+ksub][o][kk] = fp16(Wo[o][c*32+d])
//   c = sl*8 + ksub*2 + (kk>>5),  d = kk&31
// ---------------------------------------------------------------------------
__global__ __launch_bounds__(256) void wo_kernel(const float* __restrict__ Wo)
{
    __shared__ float rowv[1024];
    int o = blockIdx.x, tid = threadIdx.x;
    for (int i = tid; i < 1024; i += 256) rowv[i] = Wo[o * 1024 + i];
    __syncthreads();
    for (int r = tid; r < 1024; r += 256) {
        int cidx = r >> 6, kk = r & 63;
        int sl = cidx >> 2, ksub = cidx & 3;
        int c = sl * 8 + ksub * 2 + (kk >> 5), d = kk & 31;
        g_W[cidx * 8192 + o * 64 + kk] = __float2half(rowv[c * 32 + d]);
    }
}

// ---------------------------------------------------------------------------
// main: CTA = 8i x 8j = 64 pairs. GEMM1 (4 c-slices) -> remap -> GEMM2 (16 chunks)
// smem: As 32K | Bs 32K | Zs 32K (4 sub x 64 x 128B) | Wo 2x16K | invd 256B
// ---------------------------------------------------------------------------
#define OFF_AS 0u
#define OFF_BS 32768u
#define OFF_ZS 65536u
#define OFF_WO 98304u
#define OFF_IV 131072u
#define SMEM_BYTES (131072 + 256)

__global__ void __launch_bounds__(256, 1) main_kernel(
    const float* __restrict__ bo, float* __restrict__ out)
{
    extern __shared__ char sm[];
    const uint32_t smb = smem_u32(sm);
    const int tid = threadIdx.x, wid = tid >> 5, lane = tid & 31;
    const int i0 = blockIdx.y * 8, j0 = blockIdx.x * 8;
    float* sInvd = (float*)(sm + OFF_IV);

    // invd per pair
    if (tid < 64) {
        unsigned long long wv = g_mbits[i0 + (tid >> 3)] & g_mbits[j0 + (tid & 7)];
        sInvd[tid] = 1.f / fmaxf((float)__popcll(wv), 1.f);
    }

    // load A/B tiles (each 256 rows x 128B, contiguous in gmem), swizzled
    {
        const char* srcA = (const char*)g_A + (size_t)i0 * 4096;  // 32 rows/n * 128B
        const char* srcB = (const char*)g_B + (size_t)j0 * 4096;
        #pragma unroll
        for (int q = 0; q < 8; q++) {
            uint32_t rel = (uint32_t)(tid + q * 256) * 16u;
            uint32_t sw = SWZ(rel);
            *(uint4*)(sm + OFF_AS + sw) = *(const uint4*)(srcA + rel);
            *(uint4*)(sm + OFF_BS + sw) = *(const uint4*)(srcB + rel);
        }
    }

    // prefetch Wo chunk 0
    {
        const char* src = (const char*)g_W;
        #pragma unroll
        for (int q = 0; q < 4; q++) {
            uint32_t rel = (uint32_t)(tid + q * 256) * 16u;
            CP16(smb + OFF_WO + SWZ(rel), src + rel);
        }
        CP_COMMIT();
    }
    __syncthreads();

    const int wm = wid >> 2, wn = wid & 3;
    const int lr = lane & 15;              // ldmatrix row-in-tile
    const int lc = (lane >> 4) << 4;       // ldmatrix byte col (0/16)
    const int mrow = lane >> 2;            // C-fragment row
    const int ncol = (lane & 3) * 2;       // C-fragment col

    float acc2[2][4][4];
    #pragma unroll
    for (int a = 0; a < 2; a++)
        #pragma unroll
        for (int b = 0; b < 4; b++)
            #pragma unroll
            for (int c = 0; c < 4; c++) acc2[a][b][c] = 0.f;

    int cidx = 0;
    for (int sl = 0; sl < 4; sl++) {
        // ---- GEMM1 slice: M=64 ((i,c_l)), N=256 ((j,d)), K=64 (s) ----
        const int mb = wm * 32, nb = wn * 64;
        float acc1[2][8][4];
        #pragma unroll
        for (int a = 0; a < 2; a++)
            #pragma unroll
            for (int b = 0; b < 8; b++)
                #pragma unroll
                for (int c = 0; c < 4; c++) acc1[a][b][c] = 0.f;

        #pragma unroll
        for (int k = 0; k < 4; k++) {
            uint32_t af[2][4];
            #pragma unroll
            for (int tm = 0; tm < 2; tm++) {
                int mm = mb + tm * 16 + lr;
                int r = ((mm >> 3) << 5) + sl * 8 + (mm & 7);
                ldsm4(af[tm], smb + OFF_AS + SWZ((uint32_t)(r * 128 + k * 32 + lc)));
            }
            uint32_t bf[8][2];
            #pragma unroll
            for (int tp = 0; tp < 4; tp++) {
                uint32_t q[4];
                int nn = nb + tp * 16 + lr;
                ldsm4(q, smb + OFF_BS + SWZ((uint32_t)(nn * 128 + k * 32 + lc)));
                bf[2*tp][0] = q[0]; bf[2*tp+1][0] = q[1];
                bf[2*tp][1] = q[2]; bf[2*tp+1][1] = q[3];
            }
            #pragma unroll
            for (int tm = 0; tm < 2; tm++)
                #pragma unroll
                for (int tn = 0; tn < 8; tn++)
                    mma16816(acc1[tm][tn], af[tm], bf[tn]);
        }
        __syncthreads();   // Zs free (prev GEMM2 done via chunk-loop syncs)

        // ---- remap Z -> Zs[ksub][pair][kk] fp16 ----
        #pragma unroll
        for (int tm = 0; tm < 2; tm++) {
            #pragma unroll
            for (int tn = 0; tn < 8; tn++) {
                int nn = nb + tn * 8 + ncol;
                int j = nn >> 5, d = nn & 31;
                #pragma unroll
                for (int h = 0; h < 2; h++) {
                    int mm = mb + tm * 16 + mrow + h * 8;
                    int i = mm >> 3, cl = mm & 7;
                    uint32_t rel = (uint32_t)((i * 8 + j) * 128 + ((cl & 1) * 32 + d) * 2);
                    __half2 hv = __floats2half2_rn(acc1[tm][tn][h*2], acc1[tm][tn][h*2+1]);
                    *(__half2*)(sm + OFF_ZS + (uint32_t)(cl >> 1) * 8192u + SWZ(rel)) = hv;
                }
            }
        }
        __syncthreads();

        // ---- GEMM2 chunks: M=64 pairs, N=128 o, K=64 per chunk ----
        const int pb = wm * 32, ob = wn * 32;
        for (int ksub = 0; ksub < 4; ksub++, cidx++) {
            if (cidx + 1 < 16) {
                const char* src = (const char*)g_W + (size_t)(cidx + 1) * 16384;
                uint32_t dst = smb + OFF_WO + (uint32_t)((cidx + 1) & 1) * 16384u;
                #pragma unroll
                for (int q = 0; q < 4; q++) {
                    uint32_t rel = (uint32_t)(tid + q * 256) * 16u;
                    CP16(dst + SWZ(rel), src + rel);
                }
                CP_COMMIT();
                CP_WAIT(1);
            } else {
                CP_WAIT(0);
            }
            __syncthreads();

            uint32_t zbase = smb + OFF_ZS + (uint32_t)ksub * 8192u;
            uint32_t wbase = smb + OFF_WO + (uint32_t)(cidx & 1) * 16384u;
            #pragma unroll
            for (int k = 0; k < 4; k++) {
                uint32_t af[2][4];
                #pragma unroll
                for (int tm = 0; tm < 2; tm++) {
                    int p = pb + tm * 16 + lr;
                    ldsm4(af[tm], zbase + SWZ((uint32_t)(p * 128 + k * 32 + lc)));
                }
                uint32_t bf[4][2];
                #pragma unroll
                for (int tp = 0; tp < 2; tp++) {
                    uint32_t q[4];
                    int o = ob + tp * 16 + lr;
                    ldsm4(q, wbase + SWZ((uint32_t)(o * 128 + k * 32 + lc)));
                    bf[2*tp][0] = q[0]; bf[2*tp+1][0] = q[1];
                    bf[2*tp][1] = q[2]; bf[2*tp+1][1] = q[3];
                }
                #pragma unroll
                for (int tm = 0; tm < 2; tm++)
                    #pragma unroll
                    for (int tn = 0; tn < 4; tn++)
                        mma16816(acc2[tm][tn], af[tm], bf[tn]);
            }
            __syncthreads();   // Wo buf / Zs reuse safety
        }
    }

    // ---- epilogue: /denom, +bo, store ----
    const int pb = wm * 32, ob = wn * 32;
    float2 bo2[4];
    #pragma unroll
    for (int tn = 0; tn < 4; tn++)
        bo2[tn] = *(const float2*)(bo + ob + tn * 8 + ncol);

    #pragma unroll
    for (int tm = 0; tm < 2; tm++) {
        #pragma unroll
        for (int h = 0; h < 2; h++) {
            int pair = pb + tm * 16 + mrow + h * 8;
            int i = pair >> 3, j = pair & 7;
            float invd = sInvd[pair];
            float* op = out + ((size_t)(i0 + i) * N_DIM + (j0 + j)) * C_OUT;
            #pragma unroll
            for (int tn = 0; tn < 4; tn++) {
                float2 v;
                v.x = acc2[tm][tn][h*2]   * invd + bo2[tn].x;
                v.y = acc2[tm][tn][h*2+1] * invd + bo2[tn].y;
                *(float2*)(op + ob + tn * 8 + ncol) = v;
            }
        }
    }
}

// ---------------------------------------------------------------------------
extern "C" void kernel_launch(void* const* d_in, const int* in_sizes, int n_in,
                              void* d_out, int out_size)
{
    const float* m     = (const float*)d_in[0];
    const int*   mask  = (const int*)  d_in[1];
    const float* gamma = (const float*)d_in[2];
    const float* beta  = (const float*)d_in[3];
    const float* Wa    = (const float*)d_in[4];
    const float* Wb    = (const float*)d_in[5];
    const float* Wo    = (const float*)d_in[6];
    const float* bo    = (const float*)d_in[7];
    float* out = (float*)d_out;

    cudaFuncSetAttribute(main_kernel, cudaFuncAttributeMaxDynamicSharedMemorySize, SMEM_BYTES);

    prep_kernel<<<N_DIM, 256>>>(m, mask, gamma, beta, Wa, Wb);
    wo_kernel<<<C_OUT, 256>>>(Wo);

    dim3 grid(N_DIM / 8, N_DIM / 8);
    main_kernel<<<grid, 256, SMEM_BYTES>>>(bo, out);
}